// round 6
// baseline (speedup 1.0000x reference)
#include <cuda_runtime.h>

// Problem constants
#define N_PTS   16384
#define M_REF   4096
#define L_LAYERS 8
#define KMAX    7                    // Fourier order; trunc err ~ 6e-5 abs on e^{2cos}
#define RNK     (2*KMAX + 1)         // 15 features per coordinate
#define RPAD    16                   // padded row (float4-aligned)
#define R2      (RNK*RNK)            // 225
#define SPAD    (RNK*RPAD)           // 240
#define SBLK    32                   // producer blocks (S partials)
#define MPB     128                  // reference points per producer block
#define TPB     128
#define NBLK    (N_PTS / TPB)        // 128 blocks total (<= 148 SMs: wave-1 resident)
#define SCALE   4.4711032452e-6f     // exp(-4) / 4096

// Scratch + handshake state (device globals; restored to 0 by kernel epilogue)
__device__ float g_SpartT[R2 * SBLK];   // transposed: [e][p], 128B rows
__device__ int   g_arrive = 0;
__device__ int   g_done   = 0;

// c_0 = I_0(2), c_k = 2*I_k(2)
__constant__ float C_BES[KMAX + 1] = {
    2.27958530f, 3.18127371f, 1.37789690f, 0.42547992f,
    0.10145715f, 0.01965093f, 3.2003260e-3f, 4.4927600e-4f
};

__device__ __forceinline__ float ex2_approx(float d) {
    float r; asm("ex2.approx.ftz.f32 %0, %1;" : "=f"(r) : "f"(d)); return r;
}
__device__ __forceinline__ float rcp_approx(float d) {
    float r; asm("rcp.approx.ftz.f32 %0, %1;" : "=f"(r) : "f"(d)); return r;
}
// tanh via e^{2x}: 1 - 2/(e^{2x}+1). Saturates correctly. Rel err ~1e-6.
__device__ __forceinline__ float fast_tanh(float x) {
    float e = ex2_approx(x * 2.8853900817779268f);
    return fmaf(-2.0f, rcp_approx(e + 1.0f), 1.0f);
}

// Fourier features via MUFU sin/cos + Chebyshev recurrence.
// out[0] = w0; out[k] = w_k cos(k a); out[KMAX+k] = w_k sin(k a), k=1..KMAX.
template <bool WEIGHTED>
__device__ __forceinline__ void four_feats(float ang, float* out, float wscale) {
    float s = __sinf(ang);
    float c = __cosf(ang);
    float c2 = 2.0f * c;
    float ckm = 1.0f, skm = 0.0f;
    float ck  = c,    sk  = s;
    out[0] = WEIGHTED ? C_BES[0] * wscale : 1.0f;
    #pragma unroll
    for (int k = 1; k <= KMAX; k++) {
        float w = WEIGHTED ? C_BES[k] * wscale : 1.0f;
        out[k]        = w * ck;
        out[KMAX + k] = w * sk;
        float cn = fmaf(c2, ck, -ckm);
        float sn = fmaf(c2, sk, -skm);
        ckm = ck; skm = sk; ck = cn; sk = sn;
    }
}

// -------------------------------------------------------------------------
// Single fused kernel. Grid = 128 blocks x 128 threads (all co-resident).
//   Blocks [0,32): first produce partial S matrices -> g_SpartT, arrive++.
//   All blocks:    inline 8-layer tanh chain + u-features for their 128 n's
//                  (overlaps producer latency), spin until arrive==32,
//                  reduce S from L2, bilinear form, MLP, softmax.
//   Epilogue: last of 128 done-arrivals resets counters (replay-invariant).
// -------------------------------------------------------------------------
__global__ void __launch_bounds__(TPB) fused_kernel(
    const float* __restrict__ x,
    const float* __restrict__ layer_W,
    const float* __restrict__ layer_b,
    const float* __restrict__ layer_scale,
    const float* __restrict__ layer_shift,
    const float* __restrict__ refset,
    const float* __restrict__ W1,
    const float* __restrict__ b1,
    const float* __restrict__ W2,
    const float* __restrict__ b2,
    float* __restrict__ out)
{
    // Producer phase uses 2*MPB*RNK floats (15360 B); consumer phase reuses
    // the first SPAD floats as the reduced S. Phases separated by syncs.
    __shared__ __align__(16) float smbuf[2 * MPB * RNK];

    const int b   = blockIdx.x;
    const int tid = threadIdx.x;

    // ---------------- producer phase: blocks 0..31 ----------------
    if (b < SBLK) {
        int m = b * MPB + tid;
        float2 g = ((const float2*)refset)[m];
        float v0[RNK], v1[RNK];
        four_feats<true>(g.x, v0, SCALE);   // e^-4/M folded into v0 weights
        four_feats<true>(g.y, v1, 1.0f);
        float* V0 = smbuf;
        float* V1 = smbuf + MPB * RNK;
        #pragma unroll
        for (int i = 0; i < RNK; i++) {
            V0[tid * RNK + i] = v0[i];
            V1[tid * RNK + i] = v1[i];
        }
        __syncthreads();

        int e0 = tid;              // < 128, always valid (R2=225)
        int e1 = tid + TPB;        // valid if < 225
        int j0 = e0 / RNK, k0 = e0 - j0 * RNK;
        int j1 = e1 / RNK, k1 = e1 - j1 * RNK;
        bool has1 = (e1 < R2);

        float a0 = 0.f, a1 = 0.f, c0 = 0.f, c1 = 0.f;
        #pragma unroll 4
        for (int mm = 0; mm < MPB; mm += 2) {
            a0 = fmaf(V0[(mm + 0) * RNK + j0], V1[(mm + 0) * RNK + k0], a0);
            a1 = fmaf(V0[(mm + 1) * RNK + j0], V1[(mm + 1) * RNK + k0], a1);
            if (has1) {
                c0 = fmaf(V0[(mm + 0) * RNK + j1], V1[(mm + 0) * RNK + k1], c0);
                c1 = fmaf(V0[(mm + 1) * RNK + j1], V1[(mm + 1) * RNK + k1], c1);
            }
        }
        g_SpartT[e0 * SBLK + b] = a0 + a1;
        if (has1) g_SpartT[e1 * SBLK + b] = c0 + c1;

        __threadfence();           // publish partials before arrive
        __syncthreads();
        if (tid == 0) atomicAdd(&g_arrive, 1);
        __syncthreads();           // smbuf reuse barrier
    }

    // ---------------- per-n features (independent of S) ----------------
    int n = b * TPB + tid;
    float2 xin = ((const float2*)x)[n];
    float h0 = xin.x, h1 = xin.y;
    #pragma unroll
    for (int l = 0; l < L_LAYERS; l++) {
        float w00 = layer_W[l * 4 + 0], w01 = layer_W[l * 4 + 1];
        float w10 = layer_W[l * 4 + 2], w11 = layer_W[l * 4 + 3];
        float c0  = layer_b[l * 2 + 0],  c1  = layer_b[l * 2 + 1];
        float sc0 = layer_scale[l * 2 + 0], sc1 = layer_scale[l * 2 + 1];
        float t0  = layer_shift[l * 2 + 0], t1  = layer_shift[l * 2 + 1];
        float u0 = fast_tanh(fmaf(h0, w00, fmaf(h1, w01, c0)));
        float u1 = fast_tanh(fmaf(h0, w10, fmaf(h1, w11, c1)));
        h0 = fmaf(u0, sc0, t0);
        h1 = fmaf(u1, sc1, t1);
    }

    float u0[RNK];
    __align__(16) float u1[RPAD];
    four_feats<false>(h0, u0, 1.0f);
    four_feats<false>(h1, u1, 1.0f);
    u1[RPAD - 1] = 0.0f;

    // ---------------- wait for all producers ----------------
    if (tid == 0) {
        while (*(volatile int*)&g_arrive < SBLK) __nanosleep(32);
        __threadfence();           // acquire partials
    }
    __syncthreads();

    // ---------------- reduce S (32 partials, coalesced 128B rows) ----------
    float* S = smbuf;              // reuse as 15 x 16 padded matrix
    #pragma unroll
    for (int pass = 0; pass < 2; pass++) {
        int e = tid + pass * TPB;
        if (e < R2) {
            const float4* src = (const float4*)(g_SpartT + e * SBLK);
            float4 s0 = src[0], s1 = src[1], s2 = src[2], s3 = src[3];
            float4 s4 = src[4], s5 = src[5], s6 = src[6], s7 = src[7];
            float r = (((s0.x + s0.y) + (s0.z + s0.w)) + ((s1.x + s1.y) + (s1.z + s1.w)))
                    + (((s2.x + s2.y) + (s2.z + s2.w)) + ((s3.x + s3.y) + (s3.z + s3.w)))
                    + (((s4.x + s4.y) + (s4.z + s4.w)) + ((s5.x + s5.y) + (s5.z + s5.w)))
                    + (((s6.x + s6.y) + (s6.z + s6.w)) + ((s7.x + s7.y) + (s7.z + s7.w)));
            int j = e / RNK, k = e - j * RNK;
            S[j * RPAD + k] = r;
        } else if (e < SPAD) {
            int j = e - R2;        // zero pad column
            S[j * RPAD + (RPAD - 1)] = 0.0f;
        }
    }
    __syncthreads();

    // ---------------- bilinear form + MLP + softmax ----------------
    const float4* u1v = (const float4*)u1;
    float agg = 0.0f;
    #pragma unroll
    for (int j = 0; j < RNK; j++) {
        const float4* Sv = (const float4*)(S + j * RPAD);
        float t0 = 0.f, t1 = 0.f, t2 = 0.f, t3 = 0.f;
        #pragma unroll
        for (int q = 0; q < RPAD / 4; q++) {
            float4 sv = Sv[q];
            float4 uv = u1v[q];
            t0 = fmaf(sv.x, uv.x, t0);
            t1 = fmaf(sv.y, uv.y, t1);
            t2 = fmaf(sv.z, uv.z, t2);
            t3 = fmaf(sv.w, uv.w, t3);
        }
        agg = fmaf(u0[j], (t0 + t1) + (t2 + t3), agg);
    }

    float hh[4];
    #pragma unroll
    for (int j = 0; j < 4; j++)
        hh[j] = fast_tanh(fmaf(agg, W1[j], b1[j]));

    float l0 = b2[0], l1 = b2[1];
    #pragma unroll
    for (int j = 0; j < 4; j++) {
        l0 = fmaf(W2[j],     hh[j], l0);
        l1 = fmaf(W2[4 + j], hh[j], l1);
    }

    const float LOG2E = 1.4426950408889634f;
    float mx = fmaxf(l0, l1);
    float e0 = ex2_approx((l0 - mx) * LOG2E);
    float e1 = ex2_approx((l1 - mx) * LOG2E);
    float inv = rcp_approx(e0 + e1);
    out[2 * n + 0] = e0 * inv;
    out[2 * n + 1] = e1 * inv;

    // ---------------- epilogue: restore counters for next replay ----------
    __syncthreads();
    if (tid == 0) {
        int old = atomicAdd(&g_done, 1);
        if (old == NBLK - 1) {     // all blocks fully done; safe to reset
            g_arrive = 0;
            g_done   = 0;
            __threadfence();
        }
    }
}

// -------------------------------------------------------------------------
extern "C" void kernel_launch(void* const* d_in, const int* in_sizes, int n_in,
                              void* d_out, int out_size)
{
    const float* x           = (const float*)d_in[0];
    const float* layer_W     = (const float*)d_in[1];
    const float* layer_b     = (const float*)d_in[2];
    const float* layer_scale = (const float*)d_in[3];
    const float* layer_shift = (const float*)d_in[4];
    const float* refset      = (const float*)d_in[5];
    const float* W1          = (const float*)d_in[6];
    const float* b1          = (const float*)d_in[7];
    const float* W2          = (const float*)d_in[8];
    const float* b2          = (const float*)d_in[9];
    float* out = (float*)d_out;

    fused_kernel<<<NBLK, TPB>>>(x, layer_W, layer_b, layer_scale, layer_shift,
                                refset, W1, b1, W2, b2, out);
}

// round 7
// speedup vs baseline: 1.0099x; 1.0099x over previous
#include <cuda_runtime.h>

// Problem constants
#define N_PTS   16384
#define M_REF   4096
#define L_LAYERS 8
#define KMAX    7                    // Fourier order; trunc err ~ 6e-5 abs on e^{2cos}
#define RNK     (2*KMAX + 1)         // 15 features per coordinate
#define RPAD    16                   // padded row (float4-aligned)
#define R2      (RNK*RNK)            // 225
#define SPAD    (RNK*RPAD)           // 240
#define PBLK    64                   // producer blocks (S partials)
#define MPB     (M_REF / PBLK)       // 64 reference points per producer block
#define TPB     128
#define NBLK    (N_PTS / TPB)        // 128 consumer blocks
#define GRID    (PBLK + NBLK)        // 192 CTAs, all co-resident (occ >= 2)
#define SCALE   4.4711032452e-6f     // exp(-4) / 4096

// Scratch + handshake (device globals; counters restored to 0 by epilogue)
__device__ float g_SpartT[R2 * PBLK];   // transposed: [e][p], 256B rows
__device__ int   g_arrive = 0;
__device__ int   g_done   = 0;

// c_0 = I_0(2), c_k = 2*I_k(2)
__constant__ float C_BES[KMAX + 1] = {
    2.27958530f, 3.18127371f, 1.37789690f, 0.42547992f,
    0.10145715f, 0.01965093f, 3.2003260e-3f, 4.4927600e-4f
};

__device__ __forceinline__ float ex2_approx(float d) {
    float r; asm("ex2.approx.ftz.f32 %0, %1;" : "=f"(r) : "f"(d)); return r;
}
__device__ __forceinline__ float rcp_approx(float d) {
    float r; asm("rcp.approx.ftz.f32 %0, %1;" : "=f"(r) : "f"(d)); return r;
}
// tanh via e^{2x}: 1 - 2/(e^{2x}+1). Saturates correctly. Rel err ~1e-6.
__device__ __forceinline__ float fast_tanh(float x) {
    float e = ex2_approx(x * 2.8853900817779268f);
    return fmaf(-2.0f, rcp_approx(e + 1.0f), 1.0f);
}

// Fourier features via MUFU sin/cos + Chebyshev recurrence.
template <bool WEIGHTED>
__device__ __forceinline__ void four_feats(float ang, float* out, float wscale) {
    float s = __sinf(ang);
    float c = __cosf(ang);
    float c2 = 2.0f * c;
    float ckm = 1.0f, skm = 0.0f;
    float ck  = c,    sk  = s;
    out[0] = WEIGHTED ? C_BES[0] * wscale : 1.0f;
    #pragma unroll
    for (int k = 1; k <= KMAX; k++) {
        float w = WEIGHTED ? C_BES[k] * wscale : 1.0f;
        out[k]        = w * ck;
        out[KMAX + k] = w * sk;
        float cn = fmaf(c2, ck, -ckm);
        float sn = fmaf(c2, sk, -skm);
        ckm = ck; skm = sk; ck = cn; sk = sn;
    }
}

// -------------------------------------------------------------------------
// One launch, disjoint roles:
//   blocks [0,64):    producers — partial S over 64 refs -> g_SpartT, arrive++, exit
//   blocks [64,192):  consumers — tanh chain + u-feats (overlaps producers),
//                     wait arrive==64, reduce S, bilinear, MLP, softmax
// Epilogue: 192nd done-arrival resets counters (replay-invariant; every
// consumer has passed its wait before it can contribute to g_done).
// -------------------------------------------------------------------------
__global__ void __launch_bounds__(TPB) fused_kernel(
    const float* __restrict__ x,
    const float* __restrict__ layer_W,
    const float* __restrict__ layer_b,
    const float* __restrict__ layer_scale,
    const float* __restrict__ layer_shift,
    const float* __restrict__ refset,
    const float* __restrict__ W1,
    const float* __restrict__ b1,
    const float* __restrict__ W2,
    const float* __restrict__ b2,
    float* __restrict__ out)
{
    __shared__ __align__(16) float smbuf[2 * MPB * RNK];   // 7.5 KB (producer); S reuse (consumer)

    const int b   = blockIdx.x;
    const int tid = threadIdx.x;

    if (b < PBLK) {
        // ======================= PRODUCER =======================
        float* V0 = smbuf;
        float* V1 = smbuf + MPB * RNK;
        if (tid < MPB) {
            int m = b * MPB + tid;
            float2 g = ((const float2*)refset)[m];
            float v0[RNK], v1[RNK];
            four_feats<true>(g.x, v0, SCALE);   // e^-4/M folded into v0
            four_feats<true>(g.y, v1, 1.0f);
            #pragma unroll
            for (int i = 0; i < RNK; i++) {
                V0[tid * RNK + i] = v0[i];
                V1[tid * RNK + i] = v1[i];
            }
        }
        __syncthreads();

        int e0 = tid;              // < 128 (R2 = 225)
        int e1 = tid + TPB;        // valid if < 225
        int j0 = e0 / RNK, k0 = e0 - j0 * RNK;
        int j1 = e1 / RNK, k1 = e1 - j1 * RNK;
        bool has1 = (e1 < R2);

        float a0 = 0.f, a1 = 0.f, c0 = 0.f, c1 = 0.f;
        #pragma unroll 8
        for (int mm = 0; mm < MPB; mm += 2) {
            a0 = fmaf(V0[(mm + 0) * RNK + j0], V1[(mm + 0) * RNK + k0], a0);
            a1 = fmaf(V0[(mm + 1) * RNK + j0], V1[(mm + 1) * RNK + k0], a1);
            if (has1) {
                c0 = fmaf(V0[(mm + 0) * RNK + j1], V1[(mm + 0) * RNK + k1], c0);
                c1 = fmaf(V0[(mm + 1) * RNK + j1], V1[(mm + 1) * RNK + k1], c1);
            }
        }
        g_SpartT[e0 * PBLK + b] = a0 + a1;
        if (has1) g_SpartT[e1 * PBLK + b] = c0 + c1;

        __threadfence();           // publish partials before arrive
        __syncthreads();
        if (tid == 0) {
            atomicAdd(&g_arrive, 1);
            int old = atomicAdd(&g_done, 1);
            if (old == GRID - 1) { g_arrive = 0; g_done = 0; __threadfence(); }
        }
        return;
    }

    // ======================= CONSUMER =======================
    int n = (b - PBLK) * TPB + tid;
    float2 xin = ((const float2*)x)[n];
    float h0 = xin.x, h1 = xin.y;
    #pragma unroll
    for (int l = 0; l < L_LAYERS; l++) {
        float w00 = layer_W[l * 4 + 0], w01 = layer_W[l * 4 + 1];
        float w10 = layer_W[l * 4 + 2], w11 = layer_W[l * 4 + 3];
        float c0  = layer_b[l * 2 + 0],  c1  = layer_b[l * 2 + 1];
        float sc0 = layer_scale[l * 2 + 0], sc1 = layer_scale[l * 2 + 1];
        float t0  = layer_shift[l * 2 + 0], t1  = layer_shift[l * 2 + 1];
        float u0 = fast_tanh(fmaf(h0, w00, fmaf(h1, w01, c0)));
        float u1 = fast_tanh(fmaf(h0, w10, fmaf(h1, w11, c1)));
        h0 = fmaf(u0, sc0, t0);
        h1 = fmaf(u1, sc1, t1);
    }

    float u0[RNK];
    __align__(16) float u1[RPAD];
    four_feats<false>(h0, u0, 1.0f);
    four_feats<false>(h1, u1, 1.0f);
    u1[RPAD - 1] = 0.0f;

    // Wait for all producers
    if (tid == 0) {
        while (*(volatile int*)&g_arrive < PBLK) __nanosleep(32);
        __threadfence();           // acquire partials
    }
    __syncthreads();

    // Reduce 64 transposed partials per element (16 coalesced float4 loads)
    float* S = smbuf;              // 15 x 16 padded
    #pragma unroll
    for (int pass = 0; pass < 2; pass++) {
        int e = tid + pass * TPB;
        if (e < R2) {
            const float4* src = (const float4*)(g_SpartT + e * PBLK);
            float r0 = 0.f, r1 = 0.f, r2 = 0.f, r3 = 0.f;
            #pragma unroll
            for (int q = 0; q < PBLK / 16; q++) {      // 4 groups of 4 float4
                float4 s0 = src[4 * q + 0];
                float4 s1 = src[4 * q + 1];
                float4 s2 = src[4 * q + 2];
                float4 s3 = src[4 * q + 3];
                r0 += (s0.x + s0.y) + (s0.z + s0.w);
                r1 += (s1.x + s1.y) + (s1.z + s1.w);
                r2 += (s2.x + s2.y) + (s2.z + s2.w);
                r3 += (s3.x + s3.y) + (s3.z + s3.w);
            }
            int j = e / RNK, k = e - j * RNK;
            S[j * RPAD + k] = (r0 + r1) + (r2 + r3);
        } else if (e < SPAD) {
            int j = e - R2;        // zero pad column
            S[j * RPAD + (RPAD - 1)] = 0.0f;
        }
    }
    __syncthreads();

    // Bilinear form u0^T S u1
    const float4* u1v = (const float4*)u1;
    float agg = 0.0f;
    #pragma unroll
    for (int j = 0; j < RNK; j++) {
        const float4* Sv = (const float4*)(S + j * RPAD);
        float t0 = 0.f, t1 = 0.f, t2 = 0.f, t3 = 0.f;
        #pragma unroll
        for (int q = 0; q < RPAD / 4; q++) {
            float4 sv = Sv[q];
            float4 uv = u1v[q];
            t0 = fmaf(sv.x, uv.x, t0);
            t1 = fmaf(sv.y, uv.y, t1);
            t2 = fmaf(sv.z, uv.z, t2);
            t3 = fmaf(sv.w, uv.w, t3);
        }
        agg = fmaf(u0[j], (t0 + t1) + (t2 + t3), agg);
    }

    // Tiny MLP + 2-way softmax
    float hh[4];
    #pragma unroll
    for (int j = 0; j < 4; j++)
        hh[j] = fast_tanh(fmaf(agg, W1[j], b1[j]));

    float l0 = b2[0], l1 = b2[1];
    #pragma unroll
    for (int j = 0; j < 4; j++) {
        l0 = fmaf(W2[j],     hh[j], l0);
        l1 = fmaf(W2[4 + j], hh[j], l1);
    }

    const float LOG2E = 1.4426950408889634f;
    float mx = fmaxf(l0, l1);
    float e0 = ex2_approx((l0 - mx) * LOG2E);
    float e1 = ex2_approx((l1 - mx) * LOG2E);
    float inv = rcp_approx(e0 + e1);
    out[2 * n + 0] = e0 * inv;
    out[2 * n + 1] = e1 * inv;

    // Epilogue: done-arrive; 192nd arrival resets counters for next replay
    __syncthreads();
    if (tid == 0) {
        int old = atomicAdd(&g_done, 1);
        if (old == GRID - 1) { g_arrive = 0; g_done = 0; __threadfence(); }
    }
}

// -------------------------------------------------------------------------
extern "C" void kernel_launch(void* const* d_in, const int* in_sizes, int n_in,
                              void* d_out, int out_size)
{
    const float* x           = (const float*)d_in[0];
    const float* layer_W     = (const float*)d_in[1];
    const float* layer_b     = (const float*)d_in[2];
    const float* layer_scale = (const float*)d_in[3];
    const float* layer_shift = (const float*)d_in[4];
    const float* refset      = (const float*)d_in[5];
    const float* W1          = (const float*)d_in[6];
    const float* b1          = (const float*)d_in[7];
    const float* W2          = (const float*)d_in[8];
    const float* b2          = (const float*)d_in[9];
    float* out = (float*)d_out;

    fused_kernel<<<GRID, TPB>>>(x, layer_W, layer_b, layer_scale, layer_shift,
                                refset, W1, b1, W2, b2, out);
}